// round 11
// baseline (speedup 1.0000x reference)
#include <cuda_runtime.h>
#include <cstdint>

// Problem constants
#define M_ROWS 32
#define IN_F   8192
#define OUT_F  32768
#define NKC    256           // k-chunks of 32
// weight_packed: [OUT_F][4096] int32, low byte of each word = two int4 nibbles
//   byte t of channel o covers k=2t (low nibble), k=2t+1 (high nibble)

// ---------------------------------------------------------------------------
// Scratch: activations pre-quantized into m16n8k32 A-fragment order, plus
// deterministic per-block rowsum partials (no atomics, no zero kernel).
// g_afrag[(kc*2 + h)*32 + lane] = uint4{a0..a3} for m-tile h (rows 16h..16h+15)
// ---------------------------------------------------------------------------
__device__ uint4 g_afrag[NKC * 2 * 32];   // 256 KB
__device__ int   g_rowpart[128][M_ROWS];  // per-quant-block partial row sums

__device__ __forceinline__ int quant1(float v, float s) {
    // IEEE divide + round-half-even + clamp: matches the reference exactly.
    float r = fminf(fmaxf(rintf(__fdiv_rn(v, s)), -127.0f), 127.0f);
    return (int)r;
}

// ---------------------------------------------------------------------------
// Prologue: quantize x into A-fragment order (float4 loads) + per-block
// row-sum partials. 128 blocks x 128 threads = 16384 threads, 1 uint4 each.
// ---------------------------------------------------------------------------
__global__ __launch_bounds__(128) void quant_frag_kernel(
    const float* __restrict__ x, const float* __restrict__ act_scale)
{
    __shared__ int rowpart[M_ROWS];
    if (threadIdx.x < M_ROWS) rowpart[threadIdx.x] = 0;
    __syncthreads();

    const int t    = blockIdx.x * 128 + threadIdx.x;   // 0..16383
    const float s  = *act_scale;
    const int lane = t & 31;
    const int h    = (t >> 5) & 1;
    const int kc   = t >> 6;
    const int r0   = 16 * h + (lane >> 2);
    const int kb   = 32 * kc + (lane & 3) * 4;

    unsigned reg[4];
    #pragma unroll
    for (int i = 0; i < 4; i++) {
        const int row = r0 + 8 * (i & 1);
        const int k0  = kb + 16 * (i >> 1);
        const float4 v4 = __ldg(reinterpret_cast<const float4*>(
                                    x + (size_t)row * IN_F + k0));
        unsigned v = 0;
        v |= ((unsigned)quant1(v4.x, s) & 0xffu);
        v |= ((unsigned)quant1(v4.y, s) & 0xffu) << 8;
        v |= ((unsigned)quant1(v4.z, s) & 0xffu) << 16;
        v |= ((unsigned)quant1(v4.w, s) & 0xffu) << 24;
        reg[i] = v;
    }
    g_afrag[t] = make_uint4(reg[0], reg[1], reg[2], reg[3]);

    const int ones = 0x01010101;
    int s0 = __dp4a((int)reg[0], ones, __dp4a((int)reg[2], ones, 0));
    int s1 = __dp4a((int)reg[1], ones, __dp4a((int)reg[3], ones, 0));
    atomicAdd(&rowpart[r0], s0);          // smem atomics only
    atomicAdd(&rowpart[r0 + 8], s1);
    __syncthreads();
    if (threadIdx.x < M_ROWS)
        g_rowpart[blockIdx.x][threadIdx.x] = rowpart[threadIdx.x];
}

// Two packed words (low bytes b0,b1) -> B-fragment word [lo0,hi0,lo1,hi1],
// nibbles biased via ^8 so e = w+8 in 0..15 (signed correction in epilogue).
__device__ __forceinline__ unsigned unpack_pair(int2 v) {
    unsigned u  = __byte_perm((unsigned)v.x, (unsigned)v.y, 0x0040);
    unsigned lo =  u       & 0x00000F0Fu;
    unsigned hi = (u >> 4) & 0x00000F0Fu;
    return __byte_perm(lo, hi, 0x5140) ^ 0x08080808u;
}

__device__ __forceinline__ void mma_s8(int* d,
    unsigned a0, unsigned a1, unsigned a2, unsigned a3,
    unsigned b0, unsigned b1)
{
    asm volatile(
        "mma.sync.aligned.m16n8k32.row.col.s32.s8.s8.s32 "
        "{%0,%1,%2,%3}, {%4,%5,%6,%7}, {%8,%9}, {%0,%1,%2,%3};\n"
        : "+r"(d[0]), "+r"(d[1]), "+r"(d[2]), "+r"(d[3])
        : "r"(a0), "r"(a1), "r"(a2), "r"(a3), "r"(b0), "r"(b1));
}

__device__ __forceinline__ unsigned smem_u32(const void* p) {
    unsigned r;
    asm("{ .reg .u64 t; cvta.to.shared.u64 t, %1; cvt.u32.u64 %0, t; }"
        : "=r"(r) : "l"(p));
    return r;
}

#define CP_ASYNC16(dst, src) \
    asm volatile("cp.async.cg.shared.global [%0], [%1], 16;\n" \
                 :: "r"(dst), "l"(src))
#define CP_COMMIT() asm volatile("cp.async.commit_group;\n" ::: "memory")
#define CP_WAIT2()  asm volatile("cp.async.wait_group 2;\n"  ::: "memory")

// ---------------------------------------------------------------------------
// Main GEMM, K-split x2, cp.async-staged weights.
// 1024 CTAs x 128 threads (4 warps); warp = (chan group cg) x (k-half kh);
// each warp: 16 channels x 32 rows x 128 kc.
// Superchunk = 2 kc = 128B/chan = 2KB/warp, staged via 4 cp.async ops
// (each 512B contiguous in gmem -> 4 L1 wavefronts, vs 8/load before).
// Smem chunk (ch,u) lives at byte u*256 + ((ch+4*(u&1))&15)*16: bijective,
// and every consumer LDS.64 half-warp phase hits 16 distinct even banks.
// 4 warp-private stages, cp.async.wait_group + __syncwarp only (no CTA sync
// in the main loop). kh halves reduce through padded smem; fused epilogue.
// ---------------------------------------------------------------------------
__global__ __launch_bounds__(128, 5) void gemm_imma_kernel(
    const int*   __restrict__ wp,        // [OUT_F][4096]
    const float* __restrict__ wscale,    // [OUT_F]
    const float* __restrict__ act_scale, // [1]
    const float* __restrict__ bias,      // [OUT_F]
    float*       __restrict__ out)       // [M_ROWS][OUT_F]
{
    __shared__ alignas(16) char wstage[4][4][2048];   // [stage][warp][bytes]
    __shared__ int red[2][32][17];
    __shared__ int rsum4[4][32];

    const int tid  = threadIdx.x;
    const int lane = tid & 31;
    const int wid  = tid >> 5;
    const int kh   = wid & 1;            // k half: kc in [128*kh, 128*kh+128)
    const int cg   = wid >> 1;
    const int nb   = blockIdx.x * 32 + cg * 16;
    const int c    = lane & 3;
    const int qd   = lane >> 2;
    const int c1   = c & 1, c2 = c >> 1;

    // ---- producer setup: op i covers channels 4i..4i+3, 128B each ----
    const int pch = lane >> 3;           // 0..3 channel within op
    const int pu  = lane & 7;            // 16B chunk within channel's 128B
    const char* wsrc[4];
    unsigned    wdst[4];
    const unsigned wsmem = smem_u32(&wstage[0][wid][0]);
    #pragma unroll
    for (int i = 0; i < 4; i++) {
        wsrc[i] = reinterpret_cast<const char*>(wp)
                  + (size_t)(nb + 4 * i + pch) * 16384
                  + (size_t)kh * 8192 + pu * 16;
        wdst[i] = wsmem + pu * 256 + (((4 * i + pch) + 4 * (pu & 1)) & 15) * 16;
    }

    #define ISSUE(sc_, st_) do {                                    \
        const size_t _g = (size_t)(sc_) * 128;                      \
        const unsigned _s = (unsigned)(st_) * 8192;                 \
        CP_ASYNC16(wdst[0] + _s, wsrc[0] + _g);                     \
        CP_ASYNC16(wdst[1] + _s, wsrc[1] + _g);                     \
        CP_ASYNC16(wdst[2] + _s, wsrc[2] + _g);                     \
        CP_ASYNC16(wdst[3] + _s, wsrc[3] + _g);                     \
    } while (0)

    // ---- consumer setup ----
    // Lane (qd,c) frag load1 for half t: chunk (8t+qd, 4kc'+c2), byte 8c1;
    // load2 at +512 (u+2, same column term).
    const int coff0 = c2 * 256 + (((qd)      + 4 * c2) & 15) * 16 + 8 * c1;
    const int coff1 = c2 * 256 + (((8 + qd)  + 4 * c2) & 15) * 16 + 8 * c1;
    const uint4* afbase = g_afrag + lane + kh * (128 * 64);

    int acc[2][2][4];
    #pragma unroll
    for (int t = 0; t < 2; t++)
        #pragma unroll
        for (int h = 0; h < 2; h++)
            #pragma unroll
            for (int j = 0; j < 4; j++) acc[t][h][j] = 0;

    // Prologue: stages 0..2 in flight.
    ISSUE(0, 0); CP_COMMIT();
    ISSUE(1, 1); CP_COMMIT();
    ISSUE(2, 2); CP_COMMIT();

    for (int scb = 0; scb < 64; scb += 4) {
        #pragma unroll
        for (int s4 = 0; s4 < 4; s4++) {
            const int sc = scb + s4;
            CP_WAIT2();                 // stage sc complete (<=2 pending)
            __syncwarp();               // other lanes' chunks visible
            if (sc + 3 < 64) ISSUE(sc + 3, (s4 + 3) & 3);
            CP_COMMIT();

            const char* sb = &wstage[s4][wid][0];
            const int kcg = 2 * sc;
            const uint4 A00 = __ldg(afbase + kcg * 64);
            const uint4 A01 = __ldg(afbase + kcg * 64 + 32);
            const uint4 A10 = __ldg(afbase + kcg * 64 + 64);
            const uint4 A11 = __ldg(afbase + kcg * 64 + 96);

            // kc' = 0
            {
                const int2 w00 = *(const int2*)(sb + coff0);
                const int2 w01 = *(const int2*)(sb + coff0 + 512);
                const int2 w10 = *(const int2*)(sb + coff1);
                const int2 w11 = *(const int2*)(sb + coff1 + 512);
                const unsigned b00 = unpack_pair(w00), b01 = unpack_pair(w01);
                const unsigned b10 = unpack_pair(w10), b11 = unpack_pair(w11);
                mma_s8(acc[0][0], A00.x, A00.y, A00.z, A00.w, b00, b01);
                mma_s8(acc[0][1], A01.x, A01.y, A01.z, A01.w, b00, b01);
                mma_s8(acc[1][0], A00.x, A00.y, A00.z, A00.w, b10, b11);
                mma_s8(acc[1][1], A01.x, A01.y, A01.z, A01.w, b10, b11);
            }
            // kc' = 1
            {
                const int2 w00 = *(const int2*)(sb + 1024 + coff0);
                const int2 w01 = *(const int2*)(sb + 1024 + coff0 + 512);
                const int2 w10 = *(const int2*)(sb + 1024 + coff1);
                const int2 w11 = *(const int2*)(sb + 1024 + coff1 + 512);
                const unsigned b00 = unpack_pair(w00), b01 = unpack_pair(w01);
                const unsigned b10 = unpack_pair(w10), b11 = unpack_pair(w11);
                mma_s8(acc[0][0], A10.x, A10.y, A10.z, A10.w, b00, b01);
                mma_s8(acc[0][1], A11.x, A11.y, A11.z, A11.w, b00, b01);
                mma_s8(acc[1][0], A10.x, A10.y, A10.z, A10.w, b10, b11);
                mma_s8(acc[1][1], A11.x, A11.y, A11.z, A11.w, b10, b11);
            }
        }
    }
    #undef ISSUE

    // Cooperative rowsum reduction (deterministic partials from quant).
    {
        const int r = tid & 31, q = tid >> 5;
        int p = 0;
        #pragma unroll 8
        for (int b = 0; b < 32; b++) p += g_rowpart[q * 32 + b][r];
        rsum4[q][r] = p;
    }
    // Cross-k-half reduction through shared memory.
    if (kh == 1) {
        #pragma unroll
        for (int t = 0; t < 2; t++)
            #pragma unroll
            for (int h = 0; h < 2; h++)
                #pragma unroll
                for (int j = 0; j < 4; j++)
                    red[cg][lane][t * 8 + h * 4 + j] = acc[t][h][j];
    }
    __syncthreads();
    if (kh == 1) return;

    #pragma unroll
    for (int t = 0; t < 2; t++)
        #pragma unroll
        for (int h = 0; h < 2; h++)
            #pragma unroll
            for (int j = 0; j < 4; j++)
                acc[t][h][j] += red[cg][lane][t * 8 + h * 4 + j];

    // Epilogue: dequant + nibble-bias correction + bias, fused.
    const float s = __ldg(act_scale);
    float rs[4];
    #pragma unroll
    for (int i = 0; i < 4; i++) {
        const int row = qd + 8 * i;
        rs[i] = (float)(rsum4[0][row] + rsum4[1][row]
                        + rsum4[2][row] + rsum4[3][row]);
    }

    #pragma unroll
    for (int t = 0; t < 2; t++) {
        const int col0 = nb + 8 * t + 2 * c;
        const float sc0 = s * __ldg(wscale + col0);
        const float sc1 = s * __ldg(wscale + col0 + 1);
        const float bb0 = __ldg(bias + col0);
        const float bb1 = __ldg(bias + col0 + 1);
        #pragma unroll
        for (int h = 0; h < 2; h++) {
            #pragma unroll
            for (int j = 0; j < 4; j++) {
                const int row = 16 * h + 8 * (j >> 1) + qd;
                const float rsum = rs[2 * h + (j >> 1)];
                const float yq = (float)acc[t][h][j] - 8.0f * rsum;
                const float y  = yq * ((j & 1) ? sc1 : sc0) + ((j & 1) ? bb1 : bb0);
                out[(size_t)row * OUT_F + col0 + (j & 1)] = y;
            }
        }
    }
}

// ---------------------------------------------------------------------------
// Inputs (metadata order): x f32[32,8192], weight_packed i32[32768,4096],
// weight_scale f32[32768,1], act_scale f32[1], bias f32[32768].
// out f32[32,32768].
// ---------------------------------------------------------------------------
extern "C" void kernel_launch(void* const* d_in, const int* in_sizes, int n_in,
                              void* d_out, int out_size)
{
    const float* x  = (const float*)d_in[0];
    const int*   wpk= (const int*)  d_in[1];
    const float* ws = (const float*)d_in[2];
    const float* as = (const float*)d_in[3];
    const float* b  = (const float*)d_in[4];
    float* out      = (float*)d_out;

    quant_frag_kernel<<<128, 128>>>(x, as);
    gemm_imma_kernel<<<OUT_F / 32, 128>>>(wpk, ws, as, b, out);
}

// round 12
// speedup vs baseline: 1.0044x; 1.0044x over previous
#include <cuda_runtime.h>
#include <cstdint>

// Problem constants
#define M_ROWS 32
#define IN_F   8192
#define OUT_F  32768
#define NKC    256           // k-chunks of 32
// weight_packed: [OUT_F][4096] int32, low byte of each word = two int4 nibbles
//   byte t of channel o covers k=2t (low nibble), k=2t+1 (high nibble)

// ---------------------------------------------------------------------------
// Scratch: activations pre-quantized into m16n8k32 A-fragment order, plus
// deterministic per-block rowsum partials (no atomics, no zero kernel).
// g_afrag[(kc*2 + h)*32 + lane] = uint4{a0..a3} for m-tile h (rows 16h..16h+15)
// ---------------------------------------------------------------------------
__device__ uint4 g_afrag[NKC * 2 * 32];   // 256 KB
__device__ int   g_rowpart[128][M_ROWS];  // per-quant-block partial row sums

__device__ __forceinline__ int quant1(float v, float s) {
    // IEEE divide + round-half-even + clamp: matches the reference exactly.
    float r = fminf(fmaxf(rintf(__fdiv_rn(v, s)), -127.0f), 127.0f);
    return (int)r;
}

// ---------------------------------------------------------------------------
// Prologue: quantize x into A-fragment order (float4 loads) + per-block
// row-sum partials. 128 blocks x 128 threads = 16384 threads, 1 uint4 each.
// ---------------------------------------------------------------------------
__global__ __launch_bounds__(128) void quant_frag_kernel(
    const float* __restrict__ x, const float* __restrict__ act_scale)
{
    __shared__ int rowpart[M_ROWS];
    if (threadIdx.x < M_ROWS) rowpart[threadIdx.x] = 0;
    __syncthreads();

    const int t    = blockIdx.x * 128 + threadIdx.x;   // 0..16383
    const float s  = *act_scale;
    const int lane = t & 31;
    const int h    = (t >> 5) & 1;
    const int kc   = t >> 6;
    const int r0   = 16 * h + (lane >> 2);
    const int kb   = 32 * kc + (lane & 3) * 4;

    unsigned reg[4];
    #pragma unroll
    for (int i = 0; i < 4; i++) {
        const int row = r0 + 8 * (i & 1);
        const int k0  = kb + 16 * (i >> 1);
        const float4 v4 = __ldg(reinterpret_cast<const float4*>(
                                    x + (size_t)row * IN_F + k0));
        unsigned v = 0;
        v |= ((unsigned)quant1(v4.x, s) & 0xffu);
        v |= ((unsigned)quant1(v4.y, s) & 0xffu) << 8;
        v |= ((unsigned)quant1(v4.z, s) & 0xffu) << 16;
        v |= ((unsigned)quant1(v4.w, s) & 0xffu) << 24;
        reg[i] = v;
    }
    g_afrag[t] = make_uint4(reg[0], reg[1], reg[2], reg[3]);

    const int ones = 0x01010101;
    int s0 = __dp4a((int)reg[0], ones, __dp4a((int)reg[2], ones, 0));
    int s1 = __dp4a((int)reg[1], ones, __dp4a((int)reg[3], ones, 0));
    atomicAdd(&rowpart[r0], s0);          // smem atomics only
    atomicAdd(&rowpart[r0 + 8], s1);
    __syncthreads();
    if (threadIdx.x < M_ROWS)
        g_rowpart[blockIdx.x][threadIdx.x] = rowpart[threadIdx.x];
}

// Two packed words (low bytes b0,b1) -> B-fragment word [lo0,hi0,lo1,hi1],
// nibbles biased via ^8 so e = w+8 in 0..15 (signed correction in epilogue).
__device__ __forceinline__ unsigned unpack_pair(int2 v) {
    unsigned u  = __byte_perm((unsigned)v.x, (unsigned)v.y, 0x0040);
    unsigned lo =  u       & 0x00000F0Fu;
    unsigned hi = (u >> 4) & 0x00000F0Fu;
    return __byte_perm(lo, hi, 0x5140) ^ 0x08080808u;
}

__device__ __forceinline__ void mma_s8(int* d,
    unsigned a0, unsigned a1, unsigned a2, unsigned a3,
    unsigned b0, unsigned b1)
{
    asm volatile(
        "mma.sync.aligned.m16n8k32.row.col.s32.s8.s8.s32 "
        "{%0,%1,%2,%3}, {%4,%5,%6,%7}, {%8,%9}, {%0,%1,%2,%3};\n"
        : "+r"(d[0]), "+r"(d[1]), "+r"(d[2]), "+r"(d[3])
        : "r"(a0), "r"(a1), "r"(a2), "r"(a3), "r"(b0), "r"(b1));
}

__device__ __forceinline__ unsigned smem_u32(const void* p) {
    unsigned r;
    asm("{ .reg .u64 t; cvta.to.shared.u64 t, %1; cvt.u32.u64 %0, t; }"
        : "=r"(r) : "l"(p));
    return r;
}

#define CP_ASYNC16(dst, src) \
    asm volatile("cp.async.cg.shared.global [%0], [%1], 16;\n" \
                 :: "r"(dst), "l"(src))
#define CP_COMMIT() asm volatile("cp.async.commit_group;\n" ::: "memory")
#define CP_WAIT2()  asm volatile("cp.async.wait_group 2;\n"  ::: "memory")

// ---------------------------------------------------------------------------
// Main GEMM, K-split x2, cp.async-staged weights.
// 1024 CTAs x 128 threads (4 warps); warp = (chan group cg) x (k-half kh);
// each warp: 16 channels x 32 rows x 128 kc.
// Superchunk = 2 kc = 128B/chan = 2KB/warp, staged via 4 cp.async ops
// (each 512B contiguous in gmem -> 4 L1 wavefronts, vs 8/load before).
// Smem chunk (ch,u) lives at byte u*256 + ((ch+4*(u&1))&15)*16: bijective,
// and every consumer LDS.64 half-warp phase hits 16 distinct even banks.
// 4 warp-private stages, cp.async.wait_group + __syncwarp only (no CTA sync
// in the main loop). kh halves reduce through padded smem; fused epilogue.
// ---------------------------------------------------------------------------
__global__ __launch_bounds__(128, 5) void gemm_imma_kernel(
    const int*   __restrict__ wp,        // [OUT_F][4096]
    const float* __restrict__ wscale,    // [OUT_F]
    const float* __restrict__ act_scale, // [1]
    const float* __restrict__ bias,      // [OUT_F]
    float*       __restrict__ out)       // [M_ROWS][OUT_F]
{
    __shared__ alignas(16) char wstage[4][4][2048];   // [stage][warp][bytes]
    __shared__ int red[2][32][17];
    __shared__ int rsum4[4][32];

    const int tid  = threadIdx.x;
    const int lane = tid & 31;
    const int wid  = tid >> 5;
    const int kh   = wid & 1;            // k half: kc in [128*kh, 128*kh+128)
    const int cg   = wid >> 1;
    const int nb   = blockIdx.x * 32 + cg * 16;
    const int c    = lane & 3;
    const int qd   = lane >> 2;
    const int c1   = c & 1, c2 = c >> 1;

    // ---- producer setup: op i covers channels 4i..4i+3, 128B each ----
    const int pch = lane >> 3;           // 0..3 channel within op
    const int pu  = lane & 7;            // 16B chunk within channel's 128B
    const char* wsrc[4];
    unsigned    wdst[4];
    const unsigned wsmem = smem_u32(&wstage[0][wid][0]);
    #pragma unroll
    for (int i = 0; i < 4; i++) {
        wsrc[i] = reinterpret_cast<const char*>(wp)
                  + (size_t)(nb + 4 * i + pch) * 16384
                  + (size_t)kh * 8192 + pu * 16;
        wdst[i] = wsmem + pu * 256 + (((4 * i + pch) + 4 * (pu & 1)) & 15) * 16;
    }

    #define ISSUE(sc_, st_) do {                                    \
        const size_t _g = (size_t)(sc_) * 128;                      \
        const unsigned _s = (unsigned)(st_) * 8192;                 \
        CP_ASYNC16(wdst[0] + _s, wsrc[0] + _g);                     \
        CP_ASYNC16(wdst[1] + _s, wsrc[1] + _g);                     \
        CP_ASYNC16(wdst[2] + _s, wsrc[2] + _g);                     \
        CP_ASYNC16(wdst[3] + _s, wsrc[3] + _g);                     \
    } while (0)

    // ---- consumer setup ----
    // Lane (qd,c) frag load1 for half t: chunk (8t+qd, 4kc'+c2), byte 8c1;
    // load2 at +512 (u+2, same column term).
    const int coff0 = c2 * 256 + (((qd)      + 4 * c2) & 15) * 16 + 8 * c1;
    const int coff1 = c2 * 256 + (((8 + qd)  + 4 * c2) & 15) * 16 + 8 * c1;
    const uint4* afbase = g_afrag + lane + kh * (128 * 64);

    int acc[2][2][4];
    #pragma unroll
    for (int t = 0; t < 2; t++)
        #pragma unroll
        for (int h = 0; h < 2; h++)
            #pragma unroll
            for (int j = 0; j < 4; j++) acc[t][h][j] = 0;

    // Prologue: stages 0..2 in flight.
    ISSUE(0, 0); CP_COMMIT();
    ISSUE(1, 1); CP_COMMIT();
    ISSUE(2, 2); CP_COMMIT();

    for (int scb = 0; scb < 64; scb += 4) {
        #pragma unroll
        for (int s4 = 0; s4 < 4; s4++) {
            const int sc = scb + s4;
            CP_WAIT2();                 // stage sc complete (<=2 pending)
            __syncwarp();               // other lanes' chunks visible
            if (sc + 3 < 64) ISSUE(sc + 3, (s4 + 3) & 3);
            CP_COMMIT();

            const char* sb = &wstage[s4][wid][0];
            const int kcg = 2 * sc;
            const uint4 A00 = __ldg(afbase + kcg * 64);
            const uint4 A01 = __ldg(afbase + kcg * 64 + 32);
            const uint4 A10 = __ldg(afbase + kcg * 64 + 64);
            const uint4 A11 = __ldg(afbase + kcg * 64 + 96);

            // kc' = 0
            {
                const int2 w00 = *(const int2*)(sb + coff0);
                const int2 w01 = *(const int2*)(sb + coff0 + 512);
                const int2 w10 = *(const int2*)(sb + coff1);
                const int2 w11 = *(const int2*)(sb + coff1 + 512);
                const unsigned b00 = unpack_pair(w00), b01 = unpack_pair(w01);
                const unsigned b10 = unpack_pair(w10), b11 = unpack_pair(w11);
                mma_s8(acc[0][0], A00.x, A00.y, A00.z, A00.w, b00, b01);
                mma_s8(acc[0][1], A01.x, A01.y, A01.z, A01.w, b00, b01);
                mma_s8(acc[1][0], A00.x, A00.y, A00.z, A00.w, b10, b11);
                mma_s8(acc[1][1], A01.x, A01.y, A01.z, A01.w, b10, b11);
            }
            // kc' = 1
            {
                const int2 w00 = *(const int2*)(sb + 1024 + coff0);
                const int2 w01 = *(const int2*)(sb + 1024 + coff0 + 512);
                const int2 w10 = *(const int2*)(sb + 1024 + coff1);
                const int2 w11 = *(const int2*)(sb + 1024 + coff1 + 512);
                const unsigned b00 = unpack_pair(w00), b01 = unpack_pair(w01);
                const unsigned b10 = unpack_pair(w10), b11 = unpack_pair(w11);
                mma_s8(acc[0][0], A10.x, A10.y, A10.z, A10.w, b00, b01);
                mma_s8(acc[0][1], A11.x, A11.y, A11.z, A11.w, b00, b01);
                mma_s8(acc[1][0], A10.x, A10.y, A10.z, A10.w, b10, b11);
                mma_s8(acc[1][1], A11.x, A11.y, A11.z, A11.w, b10, b11);
            }
        }
    }
    #undef ISSUE

    // Cooperative rowsum reduction (deterministic partials from quant).
    {
        const int r = tid & 31, q = tid >> 5;
        int p = 0;
        #pragma unroll 8
        for (int b = 0; b < 32; b++) p += g_rowpart[q * 32 + b][r];
        rsum4[q][r] = p;
    }
    // Cross-k-half reduction through shared memory.
    if (kh == 1) {
        #pragma unroll
        for (int t = 0; t < 2; t++)
            #pragma unroll
            for (int h = 0; h < 2; h++)
                #pragma unroll
                for (int j = 0; j < 4; j++)
                    red[cg][lane][t * 8 + h * 4 + j] = acc[t][h][j];
    }
    __syncthreads();
    if (kh == 1) return;

    #pragma unroll
    for (int t = 0; t < 2; t++)
        #pragma unroll
        for (int h = 0; h < 2; h++)
            #pragma unroll
            for (int j = 0; j < 4; j++)
                acc[t][h][j] += red[cg][lane][t * 8 + h * 4 + j];

    // Epilogue: dequant + nibble-bias correction + bias, fused.
    const float s = __ldg(act_scale);
    float rs[4];
    #pragma unroll
    for (int i = 0; i < 4; i++) {
        const int row = qd + 8 * i;
        rs[i] = (float)(rsum4[0][row] + rsum4[1][row]
                        + rsum4[2][row] + rsum4[3][row]);
    }

    #pragma unroll
    for (int t = 0; t < 2; t++) {
        const int col0 = nb + 8 * t + 2 * c;
        const float sc0 = s * __ldg(wscale + col0);
        const float sc1 = s * __ldg(wscale + col0 + 1);
        const float bb0 = __ldg(bias + col0);
        const float bb1 = __ldg(bias + col0 + 1);
        #pragma unroll
        for (int h = 0; h < 2; h++) {
            #pragma unroll
            for (int j = 0; j < 4; j++) {
                const int row = 16 * h + 8 * (j >> 1) + qd;
                const float rsum = rs[2 * h + (j >> 1)];
                const float yq = (float)acc[t][h][j] - 8.0f * rsum;
                const float y  = yq * ((j & 1) ? sc1 : sc0) + ((j & 1) ? bb1 : bb0);
                out[(size_t)row * OUT_F + col0 + (j & 1)] = y;
            }
        }
    }
}

// ---------------------------------------------------------------------------
// Inputs (metadata order): x f32[32,8192], weight_packed i32[32768,4096],
// weight_scale f32[32768,1], act_scale f32[1], bias f32[32768].
// out f32[32,32768].
// ---------------------------------------------------------------------------
extern "C" void kernel_launch(void* const* d_in, const int* in_sizes, int n_in,
                              void* d_out, int out_size)
{
    const float* x  = (const float*)d_in[0];
    const int*   wpk= (const int*)  d_in[1];
    const float* ws = (const float*)d_in[2];
    const float* as = (const float*)d_in[3];
    const float* b  = (const float*)d_in[4];
    float* out      = (float*)d_out;

    quant_frag_kernel<<<128, 128>>>(x, as);
    gemm_imma_kernel<<<OUT_F / 32, 128>>>(wpk, ws, as, b, out);
}